// round 4
// baseline (speedup 1.0000x reference)
#include <cuda_runtime.h>
#include <cooperative_groups.h>
namespace cg = cooperative_groups;

#define SEQ   2048
#define INDIM 256
#define HID   256
#define G3    768

// Precomputed input projection gx[b][t][768] (includes bx). ~805 MB scratch.
__device__ float g_gx[(size_t)128 * SEQ * G3];

// ---- f32x2 packed helpers (SASS FFMA2 path, PTX-only) ----------------------
static __device__ __forceinline__ unsigned long long dup2(float a) {
    unsigned long long r;
    asm("mov.b64 %0, {%1, %1};" : "=l"(r) : "f"(a));
    return r;
}
static __device__ __forceinline__ void fma2(unsigned long long& d,
                                            unsigned long long a,
                                            unsigned long long b) {
    asm("fma.rn.f32x2 %0, %1, %2, %0;" : "+l"(d) : "l"(a), "l"(b));
}
static __device__ __forceinline__ float2 unp2(unsigned long long v) {
    float2 r;
    asm("mov.b64 {%0, %1}, %2;" : "=f"(r.x), "=f"(r.y) : "l"(v));
    return r;
}

static __device__ __forceinline__ unsigned smem_u32(const void* p) {
    return (unsigned)__cvta_generic_to_shared(p);
}

// mbarrier helpers (cluster-scope producer/consumer)
static __device__ __forceinline__ void mbar_init(unsigned addr, unsigned count) {
    asm volatile("mbarrier.init.shared.b64 [%0], %1;" :: "r"(addr), "r"(count) : "memory");
}
static __device__ __forceinline__ void mbar_arrive_peer(unsigned local_addr, unsigned rank) {
    unsigned remote;
    asm volatile("mapa.shared::cluster.u32 %0, %1, %2;"
                 : "=r"(remote) : "r"(local_addr), "r"(rank));
    asm volatile("mbarrier.arrive.release.cluster.shared::cluster.b64 _, [%0];"
                 :: "r"(remote) : "memory");
}
static __device__ __forceinline__ void mbar_wait(unsigned addr, unsigned parity) {
    asm volatile(
        "{\n\t"
        ".reg .pred P;\n\t"
        "W%=:\n\t"
        "mbarrier.try_wait.parity.acquire.cluster.shared::cta.b64 P, [%0], %1, 0x989680;\n\t"
        "@P bra.uni D%=;\n\t"
        "bra.uni W%=;\n\t"
        "D%=:\n\t"
        "}"
        :: "r"(addr), "r"(parity) : "memory");
}

// ---------------------------------------------------------------------------
// Phase 1: gx = x @ Wx^T + bx.  (unchanged)
// ---------------------------------------------------------------------------
#define GM 128
#define GN 64
#define APAD 132
#define BPAD 68
#define GX_SMEM ((256 * APAD + 256 * BPAD) * 4)   // 204800 B

__global__ void __launch_bounds__(256, 1)
gx_gemm(const float* __restrict__ x, const float* __restrict__ Wx,
        const float* __restrict__ bx) {
    extern __shared__ float sm[];
    float* As = sm;
    float* Bs = sm + 256 * APAD;

    const int bid = blockIdx.x;
    const int mt = bid / (G3 / GN);
    const int nt = bid % (G3 / GN);
    const long m0 = (long)mt * GM;
    const int  n0 = nt * GN;
    const int tid = threadIdx.x;

    {
        const float4* src = (const float4*)(x + m0 * INDIM);
        for (int i = tid; i < GM * (INDIM / 4); i += 256) {
            float4 v = src[i];
            int m = i >> 6;
            int k = (i & 63) << 2;
            As[(k + 0) * APAD + m] = v.x;
            As[(k + 1) * APAD + m] = v.y;
            As[(k + 2) * APAD + m] = v.z;
            As[(k + 3) * APAD + m] = v.w;
        }
    }
    {
        const float4* src = (const float4*)(Wx + (long)n0 * INDIM);
        for (int i = tid; i < GN * (INDIM / 4); i += 256) {
            float4 v = src[i];
            int n = i >> 6;
            int k = (i & 63) << 2;
            Bs[(k + 0) * BPAD + n] = v.x;
            Bs[(k + 1) * BPAD + n] = v.y;
            Bs[(k + 2) * BPAD + n] = v.z;
            Bs[(k + 3) * BPAD + n] = v.w;
        }
    }
    __syncthreads();

    const int tm = (tid & 15) * 8;
    const int tn = (tid >> 4) * 4;

    unsigned long long acc[8][2];
#pragma unroll
    for (int i = 0; i < 8; i++) { acc[i][0] = 0ull; acc[i][1] = 0ull; }

#pragma unroll 8
    for (int k = 0; k < INDIM; k++) {
        float4 a0 = *(const float4*)&As[k * APAD + tm];
        float4 a1 = *(const float4*)&As[k * APAD + tm + 4];
        ulonglong2 bv = *(const ulonglong2*)&Bs[k * BPAD + tn];
        float am[8] = {a0.x, a0.y, a0.z, a0.w, a1.x, a1.y, a1.z, a1.w};
#pragma unroll
        for (int i = 0; i < 8; i++) {
            unsigned long long ad = dup2(am[i]);
            fma2(acc[i][0], ad, bv.x);
            fma2(acc[i][1], ad, bv.y);
        }
    }

    const float b0 = bx[n0 + tn + 0], b1 = bx[n0 + tn + 1];
    const float b2 = bx[n0 + tn + 2], b3 = bx[n0 + tn + 3];
#pragma unroll
    for (int i = 0; i < 8; i++) {
        float2 lo = unp2(acc[i][0]);
        float2 hi = unp2(acc[i][1]);
        float4 o;
        o.x = lo.x + b0; o.y = lo.y + b1; o.z = hi.x + b2; o.w = hi.y + b3;
        *(float4*)&g_gx[(m0 + tm + i) * G3 + n0 + tn] = o;
    }
}

// ---------------------------------------------------------------------------
// Phase 2: persistent recurrence v3 — mbarrier sync, gx prefetch pipeline.
// 32 clusters x 4 CTAs, 768 threads. CTA owns 64 hidden units (192 gate rows).
// ---------------------------------------------------------------------------
#define CLUSTER 4
#define UB    64
#define ROWS  192
#define BPC   4
#define NTHR  768
#define WPAD  258
#define NSLC  8
#define KSL   32

#define OFF_H    (ROWS * WPAD)                  // 49536
#define OFF_P    (OFF_H + 2 * HID * BPC)        // 51584
#define OFF_BH   (OFF_P + BPC * NSLC * ROWS)    // 57728
#define OFF_MB   (OFF_BH + ROWS)                // 57920 (8B-aligned)
#define REC_SMEM ((OFF_MB + 4) * 4)             // 231696 B

__global__ void __launch_bounds__(NTHR, 1) __cluster_dims__(CLUSTER, 1, 1)
gru_rec(const float* __restrict__ Wh, const float* __restrict__ bh,
        const float* __restrict__ Wfc, const float* __restrict__ bfc,
        float* __restrict__ out) {
    extern __shared__ float sm[];
    float* ws   = sm;            // ws[r][k], r<192 local gate row, k<256
    float* hbuf = sm + OFF_H;    // hbuf[buf][k][b]: 2 x 256 x 4
    float* part = sm + OFF_P;    // part[b][c*192 + r]
    float* bhs  = sm + OFF_BH;

    cg::cluster_group cl = cg::this_cluster();
    const int rank = (int)cl.block_rank();
    const int clid = (int)blockIdx.x / CLUSTER;
    const int tid  = threadIdx.x;
    const int U0   = rank * UB;
    const int B0   = clid * BPC;

    const unsigned mbar0 = smem_u32(sm + OFF_MB);      // barrier for hbuf[0]
    const unsigned mbar1 = mbar0 + 8;                  // barrier for hbuf[1]

    // Load Wh slice: local row r -> global gate row (r/64)*256 + U0 + (r%64)
    for (int e4 = tid; e4 < ROWS * (HID / 4); e4 += NTHR) {
        int r = e4 >> 6;
        int k = (e4 & 63) << 2;
        int grow = (r / UB) * HID + U0 + (r % UB);
        float4 v = *(const float4*)&Wh[(long)grow * HID + k];
        ws[r * WPAD + k + 0] = v.x;
        ws[r * WPAD + k + 1] = v.y;
        ws[r * WPAD + k + 2] = v.z;
        ws[r * WPAD + k + 3] = v.w;
    }
    for (int r = tid; r < ROWS; r += NTHR)
        bhs[r] = bh[(r / UB) * HID + U0 + (r % UB)];
    for (int i = tid; i < 2 * HID * BPC; i += NTHR)
        hbuf[i] = 0.0f;
    if (tid == 0) {
        mbar_init(mbar0, 8 * CLUSTER);   // 8 gate warps x 4 CTAs
        mbar_init(mbar1, 8 * CLUSTER);
    }
    __syncthreads();

    const int c  = tid / 96;           // k-slice 0..7
    const int j  = tid % 96;
    const int rA = j;
    const int rB = j + 96;
    const float* wsB = ws + rB * WPAD + c * KSL;

    // Row-A weights -> registers
    float wa[KSL];
    {
        const float* wsA = ws + rA * WPAD + c * KSL;
#pragma unroll
        for (int k = 0; k < KSL; k++) wa[k] = wsA[k];
    }

    const int gu = tid & 63;           // gate-phase unit  (tid < 256)
    const int gb = tid >> 6;           // gate-phase batch (tid < 256)
    const bool is_gate = (tid < 256);

    float* peer[CLUSTER];
#pragma unroll
    for (int r = 0; r < CLUSTER; r++)
        peer[r] = (float*)cl.map_shared_rank(hbuf, r);

    cl.sync();   // mbarriers + zeroed hbuf visible cluster-wide

    unsigned ph0 = 0, ph1 = 0;

    // Prefetch gx for t=0
    float gcr = 0.f, gcz = 0.f, gcn = 0.f;
    if (is_gate) {
        const float* gp = g_gx + ((long)(B0 + gb) * SEQ + 0) * G3 + (U0 + gu);
        gcr = gp[0]; gcz = gp[256]; gcn = gp[512];
    }

    for (int t = 0; t < SEQ; t++) {
        const int cur = t & 1;
        const int nxt = cur ^ 1;

        // Issue gx prefetch for t+1 BEFORE the wait (fully hidden)
        float gnr = 0.f, gnz = 0.f, gnn = 0.f;
        if (is_gate && t + 1 < SEQ) {
            const float* gp = g_gx + ((long)(B0 + gb) * SEQ + (t + 1)) * G3 + (U0 + gu);
            gnr = gp[0]; gnz = gp[256]; gnn = gp[512];
        }

        // Wait for hbuf[cur] (produced at step t-1 by all CTAs' gates)
        if (t > 0) {
            if (cur == 0) { mbar_wait(mbar0, ph0); ph0 ^= 1; }
            else          { mbar_wait(mbar1, ph1); ph1 ^= 1; }
        }

        // Dot: 32-long k-slice, 2 rows, 4 batches (batch-packed f32x2)
        const ulonglong2* hv2 =
            (const ulonglong2*)(hbuf + cur * HID * BPC) + c * KSL;
        unsigned long long aA0 = 0ull, aA1 = 0ull, aB0 = 0ull, aB1 = 0ull;
#pragma unroll
        for (int kp = 0; kp < KSL / 2; kp++) {
            float2 wb = *(const float2*)&wsB[2 * kp];
            ulonglong2 h0 = hv2[2 * kp];
            ulonglong2 h1 = hv2[2 * kp + 1];
            unsigned long long da0 = dup2(wa[2 * kp]);
            unsigned long long da1 = dup2(wa[2 * kp + 1]);
            unsigned long long db0 = dup2(wb.x);
            unsigned long long db1 = dup2(wb.y);
            fma2(aA0, da0, h0.x); fma2(aA1, da0, h0.y);
            fma2(aB0, db0, h0.x); fma2(aB1, db0, h0.y);
            fma2(aA0, da1, h1.x); fma2(aA1, da1, h1.y);
            fma2(aB0, db1, h1.x); fma2(aB1, db1, h1.y);
        }
        {
            float2 vA01 = unp2(aA0), vA23 = unp2(aA1);
            float2 vB01 = unp2(aB0), vB23 = unp2(aB1);
            const int pb = c * ROWS;
            part[0 * 1536 + pb + rA] = vA01.x;
            part[1 * 1536 + pb + rA] = vA01.y;
            part[2 * 1536 + pb + rA] = vA23.x;
            part[3 * 1536 + pb + rA] = vA23.y;
            part[0 * 1536 + pb + rB] = vB01.x;
            part[1 * 1536 + pb + rB] = vB01.y;
            part[2 * 1536 + pb + rB] = vB23.x;
            part[3 * 1536 + pb + rB] = vB23.y;
        }
        __syncthreads();

        if (is_gate) {
            const float* pp = part + gb * 1536;
            float sr = bhs[gu], sz = bhs[64 + gu], sn = bhs[128 + gu];
#pragma unroll
            for (int cc = 0; cc < NSLC; cc++) {
                sr += pp[cc * ROWS + gu];
                sz += pp[cc * ROWS + 64 + gu];
                sn += pp[cc * ROWS + 128 + gu];
            }
            float r = __fdividef(1.0f, 1.0f + __expf(-(gcr + sr)));
            float z = __fdividef(1.0f, 1.0f + __expf(-(gcz + sz)));
            float narg = gcn + r * sn;
            float n = 2.0f * __fdividef(1.0f, 1.0f + __expf(-2.0f * narg)) - 1.0f;
            float hold = hbuf[cur * HID * BPC + (U0 + gu) * BPC + gb];
            float hnew = n + z * (hold - n);
            int off = nxt * HID * BPC + (U0 + gu) * BPC + gb;
#pragma unroll
            for (int r2 = 0; r2 < CLUSTER; r2++)
                peer[r2][off] = hnew;

            // Warp-elected release-arrive on every CTA's bar[nxt]
            __syncwarp(0xFFFFFFFFu);
            if ((tid & 31) == 0) {
                unsigned mb = (nxt == 0) ? mbar0 : mbar1;
#pragma unroll
                for (int r2 = 0; r2 < CLUSTER; r2++)
                    mbar_arrive_peer(mb, (unsigned)r2);
            }
        }
        gcr = gnr; gcz = gnz; gcn = gnn;
    }

    // Final h in hbuf[0]: wait for its last completion (armed at t=2047)
    mbar_wait(mbar0, ph0);

    if (rank == 0) {
        const int w = tid >> 5, lane = tid & 31;
        if (w < 8) {
            const int b = w >> 1, o = w & 1;
            float s = 0.f;
            for (int k = lane; k < HID; k += 32)
                s += hbuf[k * BPC + b] * __ldg(&Wfc[o * HID + k]);
#pragma unroll
            for (int d = 16; d > 0; d >>= 1)
                s += __shfl_xor_sync(0xFFFFFFFFu, s, d);
            if (lane == 0)
                out[(B0 + b) * 2 + o] = s + bfc[o];
        }
    }

    cl.sync();   // keep cluster alive until all DSMEM traffic done
}

// ---------------------------------------------------------------------------
extern "C" void kernel_launch(void* const* d_in, const int* in_sizes, int n_in,
                              void* d_out, int out_size) {
    const float* x   = (const float*)d_in[0];
    const float* Wx  = (const float*)d_in[1];
    const float* bx  = (const float*)d_in[2];
    const float* Wh  = (const float*)d_in[3];
    const float* bh  = (const float*)d_in[4];
    const float* Wfc = (const float*)d_in[5];
    const float* bfc = (const float*)d_in[6];
    float* out = (float*)d_out;

    cudaFuncSetAttribute(gx_gemm, cudaFuncAttributeMaxDynamicSharedMemorySize, GX_SMEM);
    cudaFuncSetAttribute(gru_rec, cudaFuncAttributeMaxDynamicSharedMemorySize, REC_SMEM);

    const int mtiles = (128 * SEQ) / GM;     // 2048
    const int ntiles = G3 / GN;              // 12
    gx_gemm<<<mtiles * ntiles, 256, GX_SMEM>>>(x, Wx, bx);
    gru_rec<<<32 * CLUSTER, NTHR, REC_SMEM>>>(Wh, bh, Wfc, bfc, out);
}

// round 5
// speedup vs baseline: 1.0096x; 1.0096x over previous
#include <cuda_runtime.h>
#include <cooperative_groups.h>
namespace cg = cooperative_groups;

#define SEQ   2048
#define INDIM 256
#define HID   256
#define G3    768

// Precomputed input projection gx[b][t][768] (includes bx). ~805 MB scratch.
__device__ float g_gx[(size_t)128 * SEQ * G3];

// ---- f32x2 packed helpers (SASS FFMA2 path, PTX-only) ----------------------
static __device__ __forceinline__ unsigned long long dup2(float a) {
    unsigned long long r;
    asm("mov.b64 %0, {%1, %1};" : "=l"(r) : "f"(a));
    return r;
}
static __device__ __forceinline__ void fma2(unsigned long long& d,
                                            unsigned long long a,
                                            unsigned long long b) {
    asm("fma.rn.f32x2 %0, %1, %2, %0;" : "+l"(d) : "l"(a), "l"(b));
}
static __device__ __forceinline__ float2 unp2(unsigned long long v) {
    float2 r;
    asm("mov.b64 {%0, %1}, %2;" : "=f"(r.x), "=f"(r.y) : "l"(v));
    return r;
}

// ---- cluster barrier (split arrive/wait) -----------------------------------
static __device__ __forceinline__ void cluster_arrive() {
    asm volatile("barrier.cluster.arrive.aligned;" ::: "memory");
}
static __device__ __forceinline__ void cluster_wait() {
    asm volatile("barrier.cluster.wait.aligned;" ::: "memory");
}
// named CTA barrier: producers arrive, consumers sync
static __device__ __forceinline__ void bar_arrive(int id, int cnt) {
    asm volatile("bar.arrive %0, %1;" :: "r"(id), "r"(cnt) : "memory");
}
static __device__ __forceinline__ void bar_sync(int id, int cnt) {
    asm volatile("bar.sync %0, %1;" :: "r"(id), "r"(cnt) : "memory");
}

// ---------------------------------------------------------------------------
// Phase 1: gx = x @ Wx^T + bx.  (unchanged)
// ---------------------------------------------------------------------------
#define GM 128
#define GN 64
#define APAD 132
#define BPAD 68
#define GX_SMEM ((256 * APAD + 256 * BPAD) * 4)   // 204800 B

__global__ void __launch_bounds__(256, 1)
gx_gemm(const float* __restrict__ x, const float* __restrict__ Wx,
        const float* __restrict__ bx) {
    extern __shared__ float sm[];
    float* As = sm;
    float* Bs = sm + 256 * APAD;

    const int bid = blockIdx.x;
    const int mt = bid / (G3 / GN);
    const int nt = bid % (G3 / GN);
    const long m0 = (long)mt * GM;
    const int  n0 = nt * GN;
    const int tid = threadIdx.x;

    {
        const float4* src = (const float4*)(x + m0 * INDIM);
        for (int i = tid; i < GM * (INDIM / 4); i += 256) {
            float4 v = src[i];
            int m = i >> 6;
            int k = (i & 63) << 2;
            As[(k + 0) * APAD + m] = v.x;
            As[(k + 1) * APAD + m] = v.y;
            As[(k + 2) * APAD + m] = v.z;
            As[(k + 3) * APAD + m] = v.w;
        }
    }
    {
        const float4* src = (const float4*)(Wx + (long)n0 * INDIM);
        for (int i = tid; i < GN * (INDIM / 4); i += 256) {
            float4 v = src[i];
            int n = i >> 6;
            int k = (i & 63) << 2;
            Bs[(k + 0) * BPAD + n] = v.x;
            Bs[(k + 1) * BPAD + n] = v.y;
            Bs[(k + 2) * BPAD + n] = v.z;
            Bs[(k + 3) * BPAD + n] = v.w;
        }
    }
    __syncthreads();

    const int tm = (tid & 15) * 8;
    const int tn = (tid >> 4) * 4;

    unsigned long long acc[8][2];
#pragma unroll
    for (int i = 0; i < 8; i++) { acc[i][0] = 0ull; acc[i][1] = 0ull; }

#pragma unroll 8
    for (int k = 0; k < INDIM; k++) {
        float4 a0 = *(const float4*)&As[k * APAD + tm];
        float4 a1 = *(const float4*)&As[k * APAD + tm + 4];
        ulonglong2 bv = *(const ulonglong2*)&Bs[k * BPAD + tn];
        float am[8] = {a0.x, a0.y, a0.z, a0.w, a1.x, a1.y, a1.z, a1.w};
#pragma unroll
        for (int i = 0; i < 8; i++) {
            unsigned long long ad = dup2(am[i]);
            fma2(acc[i][0], ad, bv.x);
            fma2(acc[i][1], ad, bv.y);
        }
    }

    const float b0 = bx[n0 + tn + 0], b1 = bx[n0 + tn + 1];
    const float b2 = bx[n0 + tn + 2], b3 = bx[n0 + tn + 3];
#pragma unroll
    for (int i = 0; i < 8; i++) {
        float2 lo = unp2(acc[i][0]);
        float2 hi = unp2(acc[i][1]);
        float4 o;
        o.x = lo.x + b0; o.y = lo.y + b1; o.z = hi.x + b2; o.w = hi.y + b3;
        *(float4*)&g_gx[(m0 + tm + i) * G3 + n0 + tn] = o;
    }
}

// ---------------------------------------------------------------------------
// Phase 2: persistent recurrence v4.
// 32 clusters x 4 CTAs, 768 threads. CTA owns 64 hidden units (192 gate rows).
// Thread (s = tid/192 in 0..3, r = tid%192) computes k-slice [64s,64s+64) for
// row r, 4 batches packed in f32x2. Sync per step: producers bar.arrive,
// gate warps bar.sync; cluster barrier split arrive(end)/wait(top) with the
// gx prefetch issued before the wait.
// ---------------------------------------------------------------------------
#define CLUSTER 4
#define UB    64
#define ROWS  192
#define BPC   4
#define NTHR  768
#define WPAD  258
#define NSLC  4

#define OFF_H    (ROWS * WPAD)                  // 49536
#define OFF_P    (OFF_H + 2 * HID * BPC)        // 51584
#define OFF_BH   (OFF_P + BPC * NSLC * ROWS)    // 54656
#define REC_SMEM ((OFF_BH + ROWS) * 4)          // 219392 B

__global__ void __launch_bounds__(NTHR, 1) __cluster_dims__(CLUSTER, 1, 1)
gru_rec(const float* __restrict__ Wh, const float* __restrict__ bh,
        const float* __restrict__ Wfc, const float* __restrict__ bfc,
        float* __restrict__ out) {
    extern __shared__ float sm[];
    float* ws   = sm;            // ws[r][k], r<192 local gate row, k<256
    float* hbuf = sm + OFF_H;    // hbuf[buf][k][b]: 2 x 256 x 4
    float* part = sm + OFF_P;    // part[b][s*192 + r]
    float* bhs  = sm + OFF_BH;

    cg::cluster_group cl = cg::this_cluster();
    const int rank = (int)cl.block_rank();
    const int clid = (int)blockIdx.x / CLUSTER;
    const int tid  = threadIdx.x;
    const int U0   = rank * UB;
    const int B0   = clid * BPC;

    // Load Wh slice: local row r -> global gate row (r/64)*256 + U0 + (r%64)
    for (int e4 = tid; e4 < ROWS * (HID / 4); e4 += NTHR) {
        int r = e4 >> 6;
        int k = (e4 & 63) << 2;
        int grow = (r / UB) * HID + U0 + (r % UB);
        float4 v = *(const float4*)&Wh[(long)grow * HID + k];
        ws[r * WPAD + k + 0] = v.x;
        ws[r * WPAD + k + 1] = v.y;
        ws[r * WPAD + k + 2] = v.z;
        ws[r * WPAD + k + 3] = v.w;
    }
    for (int r = tid; r < ROWS; r += NTHR)
        bhs[r] = bh[(r / UB) * HID + U0 + (r % UB)];
    for (int i = tid; i < 2 * HID * BPC; i += NTHR)
        hbuf[i] = 0.0f;
    __syncthreads();

    const int s = tid / ROWS;           // k-slice 0..3 (warp-uniform)
    const int r = tid % ROWS;           // gate row
    const float* wrow = ws + r * WPAD + s * 64;

    // First 32 weights of the slice -> registers
    float wa[32];
#pragma unroll
    for (int k = 0; k < 32; k++) wa[k] = wrow[k];
    const float2* wsB = (const float2*)(wrow + 32);   // 8B aligned (even offs)

    const int gu = tid & 63;            // gate-phase unit  (tid < 256)
    const int gb = tid >> 6;            // gate-phase batch (tid < 256)
    const bool is_gate = (tid < 256);

    float* peer[CLUSTER];
#pragma unroll
    for (int rr = 0; rr < CLUSTER; rr++)
        peer[rr] = (float*)cl.map_shared_rank(hbuf, rr);

    cluster_arrive();                   // primes the first loop-top wait

    // gx pointer for this gate thread
    const float* gxp = g_gx + ((long)(B0 + gb) * SEQ) * G3 + (U0 + gu);

    for (int t = 0; t < SEQ; t++) {
        const int cur = t & 1;
        const int nxt = cur ^ 1;

        // Issue gx prefetch for step t BEFORE the cluster wait
        float gcr = 0.f, gcz = 0.f, gcn = 0.f;
        if (is_gate) {
            const float* gp = gxp + (long)t * G3;
            gcr = gp[0]; gcz = gp[256]; gcn = gp[512];
        }

        cluster_wait();                 // h(t) complete in all CTAs

        // Dot: 64-long k-slice, 1 row, 4 batches (batch-packed f32x2)
        const ulonglong2* hv2 =
            (const ulonglong2*)(hbuf + cur * HID * BPC) + s * 64;
        unsigned long long a01 = 0ull, a23 = 0ull;
#pragma unroll
        for (int i = 0; i < 32; i += 2) {
            float2 wb = wsB[i >> 1];
            ulonglong2 h0 = hv2[i];
            ulonglong2 h1 = hv2[i + 1];
            ulonglong2 h2 = hv2[32 + i];
            ulonglong2 h3 = hv2[32 + i + 1];
            unsigned long long d0 = dup2(wa[i]);
            unsigned long long d1 = dup2(wa[i + 1]);
            unsigned long long d2 = dup2(wb.x);
            unsigned long long d3 = dup2(wb.y);
            fma2(a01, d0, h0.x); fma2(a23, d0, h0.y);
            fma2(a01, d1, h1.x); fma2(a23, d1, h1.y);
            fma2(a01, d2, h2.x); fma2(a23, d2, h2.y);
            fma2(a01, d3, h3.x); fma2(a23, d3, h3.y);
        }
        {
            float2 v01 = unp2(a01), v23 = unp2(a23);
            const int pb = s * ROWS + r;
            part[0 * 768 + pb] = v01.x;
            part[1 * 768 + pb] = v01.y;
            part[2 * 768 + pb] = v23.x;
            part[3 * 768 + pb] = v23.y;
        }

        if (is_gate) {
            bar_sync(1, NTHR);          // wait for all part producers
            const float* pp = part + gb * 768;
            float sr = bhs[gu]       + pp[gu]            + pp[192 + gu]
                                     + pp[384 + gu]      + pp[576 + gu];
            float sz = bhs[64 + gu]  + pp[64 + gu]       + pp[192 + 64 + gu]
                                     + pp[384 + 64 + gu] + pp[576 + 64 + gu];
            float sn = bhs[128 + gu] + pp[128 + gu]      + pp[192 + 128 + gu]
                                     + pp[384 + 128 + gu]+ pp[576 + 128 + gu];
            float rg = __fdividef(1.0f, 1.0f + __expf(-(gcr + sr)));
            float zg = __fdividef(1.0f, 1.0f + __expf(-(gcz + sz)));
            float narg = gcn + rg * sn;
            float ng = 2.0f * __fdividef(1.0f, 1.0f + __expf(-2.0f * narg)) - 1.0f;
            float hold = hbuf[cur * HID * BPC + (U0 + gu) * BPC + gb];
            float hnew = ng + zg * (hold - ng);
            int off = nxt * HID * BPC + (U0 + gu) * BPC + gb;
#pragma unroll
            for (int rr = 0; rr < CLUSTER; rr++)
                peer[rr][off] = hnew;
        } else {
            bar_arrive(1, NTHR);        // non-blocking producer arrive
        }

        cluster_arrive();               // release h(t+1); matched at next top
    }

    cluster_wait();                     // final h complete everywhere

    // Final h in hbuf[0] (t=2047: nxt=0). Rank 0 emits out[b][2].
    if (rank == 0) {
        const int w = tid >> 5, lane = tid & 31;
        if (w < 8) {
            const int b = w >> 1, o = w & 1;
            float sfc = 0.f;
            for (int k = lane; k < HID; k += 32)
                sfc += hbuf[k * BPC + b] * __ldg(&Wfc[o * HID + k]);
#pragma unroll
            for (int d = 16; d > 0; d >>= 1)
                sfc += __shfl_xor_sync(0xFFFFFFFFu, sfc, d);
            if (lane == 0)
                out[(B0 + b) * 2 + o] = sfc + bfc[o];
        }
    }
}

// ---------------------------------------------------------------------------
extern "C" void kernel_launch(void* const* d_in, const int* in_sizes, int n_in,
                              void* d_out, int out_size) {
    const float* x   = (const float*)d_in[0];
    const float* Wx  = (const float*)d_in[1];
    const float* bx  = (const float*)d_in[2];
    const float* Wh  = (const float*)d_in[3];
    const float* bh  = (const float*)d_in[4];
    const float* Wfc = (const float*)d_in[5];
    const float* bfc = (const float*)d_in[6];
    float* out = (float*)d_out;

    cudaFuncSetAttribute(gx_gemm, cudaFuncAttributeMaxDynamicSharedMemorySize, GX_SMEM);
    cudaFuncSetAttribute(gru_rec, cudaFuncAttributeMaxDynamicSharedMemorySize, REC_SMEM);

    const int mtiles = (128 * SEQ) / GM;     // 2048
    const int ntiles = G3 / GN;              // 12
    gx_gemm<<<mtiles * ntiles, 256, GX_SMEM>>>(x, Wx, bx);
    gru_rec<<<32 * CLUSTER, NTHR, REC_SMEM>>>(Wh, bh, Wfc, bfc, out);
}